// round 1
// baseline (speedup 1.0000x reference)
#include <cuda_runtime.h>
#include <cstddef>

#define N_NODES 100000
#define N_EDGES 1600000

// ---------------- scratch (static device allocs; no cudaMalloc allowed) ----
__device__ float g_t1[(size_t)N_NODES * 128];     // x @ W_neigh1
__device__ float g_hself1[(size_t)N_NODES * 128]; // x @ W_self1 + b1
__device__ float g_t2[(size_t)N_NODES * 64];      // h1_relu @ W_neigh2
__device__ float g_hself2[(size_t)N_NODES * 64];  // h1_relu @ W_self2 + b2
__device__ int   g_deg[N_NODES];
__device__ int   g_off[N_NODES + 1];
__device__ int   g_cur[N_NODES];
__device__ int   g_ssrc[N_EDGES];

// ---------------- CSR build ------------------------------------------------
__global__ void zero_deg_kernel() {
    int i = blockIdx.x * blockDim.x + threadIdx.x;
    if (i < N_NODES) g_deg[i] = 0;
}

__global__ void count_deg_kernel(const int* __restrict__ dst) {
    int e = blockIdx.x * blockDim.x + threadIdx.x;
    if (e < N_EDGES) atomicAdd(&g_deg[dst[e]], 1);
}

// single-block exclusive scan over 100k degrees (1024 threads, chunked)
__global__ void scan_offsets_kernel() {
    __shared__ int part[1024];
    const int tid = threadIdx.x;
    const int CH = (N_NODES + 1023) / 1024;  // 98
    int beg = tid * CH;
    int end = beg + CH; if (end > N_NODES) end = N_NODES;
    if (beg > N_NODES) beg = N_NODES;

    int s = 0;
    for (int i = beg; i < end; i++) s += g_deg[i];
    part[tid] = s;
    __syncthreads();
    // Hillis-Steele inclusive scan
    for (int off = 1; off < 1024; off <<= 1) {
        int v = (tid >= off) ? part[tid - off] : 0;
        __syncthreads();
        part[tid] += v;
        __syncthreads();
    }
    int run = (tid == 0) ? 0 : part[tid - 1];  // exclusive prefix
    for (int i = beg; i < end; i++) {
        g_off[i] = run;
        g_cur[i] = run;
        run += g_deg[i];
    }
    if (tid == 1023) g_off[N_NODES] = run;  // == N_EDGES
}

__global__ void fill_csr_kernel(const int* __restrict__ src,
                                const int* __restrict__ dst) {
    int e = blockIdx.x * blockDim.x + threadIdx.x;
    if (e < N_EDGES) {
        int p = atomicAdd(&g_cur[dst[e]], 1);
        g_ssrc[p] = src[e];
    }
}

// ---------------- tiled SGEMM: C[M,N] = A[M,128] @ B[128,N] (+bias) --------
// BM=128 BN=64 BK=8, 256 threads, 8x4 per-thread register tile
__global__ __launch_bounds__(256)
void sgemm_k128(const float* __restrict__ A, const float* __restrict__ B,
                const float* __restrict__ bias, float* __restrict__ C,
                int M, int N) {
    constexpr int BM = 128, BN = 64, BK = 8, TM = 8, TN = 4;
    constexpr int K = 128;
    __shared__ float As[BK][BM];
    __shared__ float Bs[BK][BN];

    const int tid = threadIdx.x;
    const int block_row = blockIdx.x * BM;
    const int block_col = blockIdx.y * BN;

    // A tile load mapping: 128 rows x 2 float4 = 256 float4 -> one per thread
    const int aRow = tid >> 1;
    const int aCol = (tid & 1) * 4;
    // B tile load mapping: 8 rows x 16 float4 = 128 float4 -> threads 0..127
    const int bRow = tid >> 4;
    const int bCol = (tid & 15) * 4;

    const int threadRow = (tid / (BN / TN)) * TM;  // 0..120 step 8
    const int threadCol = (tid % (BN / TN)) * TN;  // 0..60 step 4

    float acc[TM][TN] = {};
    float regM[TM], regN[TN];

    for (int k0 = 0; k0 < K; k0 += BK) {
        int gr = block_row + aRow;
        float4 av = make_float4(0.f, 0.f, 0.f, 0.f);
        if (gr < M)
            av = *reinterpret_cast<const float4*>(A + (size_t)gr * K + k0 + aCol);
        As[aCol + 0][aRow] = av.x;
        As[aCol + 1][aRow] = av.y;
        As[aCol + 2][aRow] = av.z;
        As[aCol + 3][aRow] = av.w;
        if (tid < 128) {
            float4 bv = *reinterpret_cast<const float4*>(
                B + (size_t)(k0 + bRow) * N + block_col + bCol);
            *reinterpret_cast<float4*>(&Bs[bRow][bCol]) = bv;
        }
        __syncthreads();
#pragma unroll
        for (int kk = 0; kk < BK; kk++) {
#pragma unroll
            for (int i = 0; i < TM; i++) regM[i] = As[kk][threadRow + i];
#pragma unroll
            for (int j = 0; j < TN; j++) regN[j] = Bs[kk][threadCol + j];
#pragma unroll
            for (int i = 0; i < TM; i++)
#pragma unroll
                for (int j = 0; j < TN; j++)
                    acc[i][j] += regM[i] * regN[j];
        }
        __syncthreads();
    }

    float bv[TN] = {0.f, 0.f, 0.f, 0.f};
    if (bias) {
#pragma unroll
        for (int j = 0; j < TN; j++) bv[j] = bias[block_col + threadCol + j];
    }
#pragma unroll
    for (int i = 0; i < TM; i++) {
        int r = block_row + threadRow + i;
        if (r >= M) continue;
        float4 out;
        out.x = acc[i][0] + bv[0];
        out.y = acc[i][1] + bv[1];
        out.z = acc[i][2] + bv[2];
        out.w = acc[i][3] + bv[3];
        *reinterpret_cast<float4*>(C + (size_t)r * N + block_col + threadCol) = out;
    }
}

// ---------------- layer-1 gather+combine: warp per dst node (D=128) --------
__global__ __launch_bounds__(256)
void gather_combine1(const float* __restrict__ hself,
                     const float* __restrict__ t,
                     float* __restrict__ out_h1,
                     float* __restrict__ out_h1r) {
    int warp = (blockIdx.x * blockDim.x + threadIdx.x) >> 5;
    int lane = threadIdx.x & 31;
    if (warp >= N_NODES) return;
    const int n = warp;
    const int beg = g_off[n];
    const int end = g_off[n + 1];

    float4 acc = make_float4(0.f, 0.f, 0.f, 0.f);
    for (int e = beg; e < end; e++) {
        int s = g_ssrc[e];  // warp-uniform broadcast load
        float4 v = *reinterpret_cast<const float4*>(t + (size_t)s * 128 + lane * 4);
        acc.x += v.x; acc.y += v.y; acc.z += v.z; acc.w += v.w;
    }
    float deg = (float)(end - beg);
    float inv = 1.0f / fmaxf(deg, 1.0f);
    float4 hs = *reinterpret_cast<const float4*>(hself + (size_t)n * 128 + lane * 4);
    float4 h1;
    h1.x = hs.x + acc.x * inv;
    h1.y = hs.y + acc.y * inv;
    h1.z = hs.z + acc.z * inv;
    h1.w = hs.w + acc.w * inv;
    *reinterpret_cast<float4*>(out_h1 + (size_t)n * 128 + lane * 4) = h1;
    float4 r;
    r.x = fmaxf(h1.x, 0.f); r.y = fmaxf(h1.y, 0.f);
    r.z = fmaxf(h1.z, 0.f); r.w = fmaxf(h1.w, 0.f);
    *reinterpret_cast<float4*>(out_h1r + (size_t)n * 128 + lane * 4) = r;
}

// ---------------- layer-2 gather+combine: warp per dst node (D=64) ---------
__global__ __launch_bounds__(256)
void gather_combine2(const float* __restrict__ hself,
                     const float* __restrict__ t,
                     float* __restrict__ out_a,
                     float* __restrict__ out_b) {
    int warp = (blockIdx.x * blockDim.x + threadIdx.x) >> 5;
    int lane = threadIdx.x & 31;
    if (warp >= N_NODES) return;
    const int n = warp;
    const int beg = g_off[n];
    const int end = g_off[n + 1];

    float2 acc = make_float2(0.f, 0.f);
    for (int e = beg; e < end; e++) {
        int s = g_ssrc[e];
        float2 v = *reinterpret_cast<const float2*>(t + (size_t)s * 64 + lane * 2);
        acc.x += v.x; acc.y += v.y;
    }
    float deg = (float)(end - beg);
    float inv = 1.0f / fmaxf(deg, 1.0f);
    float2 hs = *reinterpret_cast<const float2*>(hself + (size_t)n * 64 + lane * 2);
    float2 h2;
    h2.x = hs.x + acc.x * inv;
    h2.y = hs.y + acc.y * inv;
    *reinterpret_cast<float2*>(out_a + (size_t)n * 64 + lane * 2) = h2;
    *reinterpret_cast<float2*>(out_b + (size_t)n * 64 + lane * 2) = h2;
}

// ---------------- launch ---------------------------------------------------
extern "C" void kernel_launch(void* const* d_in, const int* in_sizes, int n_in,
                              void* d_out, int out_size) {
    const float* x        = (const float*)d_in[0];
    const float* W_self1  = (const float*)d_in[1];
    const float* W_neigh1 = (const float*)d_in[2];
    const float* b1       = (const float*)d_in[3];
    const float* W_self2  = (const float*)d_in[4];
    const float* W_neigh2 = (const float*)d_in[5];
    const float* b2       = (const float*)d_in[6];
    const int*   src      = (const int*)d_in[7];
    const int*   dst      = (const int*)d_in[8];

    float* out = (float*)d_out;
    // reference returns (h2, h1, h1_relu, h2) flattened in order
    float* out_h2a = out;                                     // 100000*64
    float* out_h1  = out + (size_t)N_NODES * 64;              // 100000*128
    float* out_h1r = out + (size_t)N_NODES * (64 + 128);      // 100000*128
    float* out_h2b = out + (size_t)N_NODES * (64 + 128 + 128);// 100000*64

    float* t1  = nullptr, *hs1 = nullptr, *t2 = nullptr, *hs2 = nullptr;
    cudaGetSymbolAddress((void**)&t1,  g_t1);
    cudaGetSymbolAddress((void**)&hs1, g_hself1);
    cudaGetSymbolAddress((void**)&t2,  g_t2);
    cudaGetSymbolAddress((void**)&hs2, g_hself2);

    // --- CSR build (shared by both layers) ---
    zero_deg_kernel<<<(N_NODES + 255) / 256, 256>>>();
    count_deg_kernel<<<(N_EDGES + 255) / 256, 256>>>(dst);
    scan_offsets_kernel<<<1, 1024>>>();
    fill_csr_kernel<<<(N_EDGES + 255) / 256, 256>>>(src, dst);

    // --- layer 1 GEMMs: hself1 = x@W_self1+b1 ; t1 = x@W_neigh1 ---
    dim3 g1((N_NODES + 127) / 128, 128 / 64);
    sgemm_k128<<<g1, 256>>>(x, W_self1,  b1,      hs1, N_NODES, 128);
    sgemm_k128<<<g1, 256>>>(x, W_neigh1, nullptr, t1,  N_NODES, 128);

    // --- layer 1 gather + combine + relu ---
    int gblocks = (N_NODES * 32 + 255) / 256;  // one warp per node
    gather_combine1<<<gblocks, 256>>>(hs1, t1, out_h1, out_h1r);

    // --- layer 2 GEMMs on h1_relu (read from d_out) ---
    dim3 g2((N_NODES + 127) / 128, 64 / 64);
    sgemm_k128<<<g2, 256>>>(out_h1r, W_self2,  b2,      hs2, N_NODES, 64);
    sgemm_k128<<<g2, 256>>>(out_h1r, W_neigh2, nullptr, t2,  N_NODES, 64);

    // --- layer 2 gather + combine ---
    gather_combine2<<<gblocks, 256>>>(hs2, t2, out_h2a, out_h2b);
}